// round 4
// baseline (speedup 1.0000x reference)
#include <cuda_runtime.h>

// ---------------- problem constants (fixed by dataset) ----------------
#define T_TOK 4096      // B*S tokens
#define DIMV  4096
#define HQ    32
#define KVH   8
#define HDIM  128
#define BATCH 2
#define SEQ   2048
#define WIN   1024

// ---------------- scratch (device globals: allocation-free) ----------------
__device__ float g_q [(size_t)T_TOK * HQ  * HDIM];   // 67 MB
__device__ float g_k [(size_t)T_TOK * KVH * HDIM];   // 17 MB
__device__ float g_v [(size_t)T_TOK * KVH * HDIM];   // 17 MB
__device__ float g_ao[(size_t)T_TOK * HQ  * HDIM];   // 67 MB

typedef unsigned long long ull;

// ---------------- packed f32x2 helpers (sm_100+) ----------------
__device__ __forceinline__ ull pack2(float x) {
    ull r; asm("mov.b64 %0, {%1, %1};" : "=l"(r) : "f"(x)); return r;
}
__device__ __forceinline__ float2 unpack2(ull v) {
    float2 r; asm("mov.b64 {%0, %1}, %2;" : "=f"(r.x), "=f"(r.y) : "l"(v)); return r;
}
__device__ __forceinline__ void fma2(ull& d, ull a, ull b) {
    asm("fma.rn.f32x2 %0, %1, %2, %0;" : "+l"(d) : "l"(a), "l"(b));
}
__device__ __forceinline__ ull mul2(ull a, ull b) {
    ull d; asm("mul.rn.f32x2 %0, %1, %2;" : "=l"(d) : "l"(a), "l"(b)); return d;
}

// ---------------- fp32 SGEMM: C[M,N] = A[M,K] @ B[K,N], all row-major ----------------
// 128x128 tile, BK=8, 256 threads, 8x8 micro-tile per thread packed as 8x4 f32x2.
// M,N multiples of 128; K multiple of 8.
__global__ __launch_bounds__(256) void sgemm128(
    const float* __restrict__ A, const float* __restrict__ B, float* __restrict__ C,
    int M, int N, int K)
{
    __shared__ float As[8][128];   // A tile transposed: As[k][m]
    __shared__ float Bs[8][128];   // B tile: Bs[k][n]

    const int tid  = threadIdx.x;
    const int bm   = blockIdx.y * 128;
    const int bn   = blockIdx.x * 128;
    const int arow = tid >> 1;            // 0..127
    const int acol = (tid & 1) * 4;       // 0 or 4
    const int brow = tid >> 5;            // 0..7
    const int bcol = (tid & 31) * 4;      // 0..124
    const int tx   = tid & 15;
    const int ty   = tid >> 4;

    ull acc[8][4];
#pragma unroll
    for (int r = 0; r < 8; r++)
#pragma unroll
        for (int c = 0; c < 4; c++) acc[r][c] = 0ull;

    const float* Ap = A + (size_t)(bm + arow) * K + acol;
    const float* Bp = B + (size_t)brow * N + bn + bcol;

    for (int kt = 0; kt < K; kt += 8) {
        float4 av = *(const float4*)(Ap + kt);
        float4 bv = *(const float4*)(Bp + (size_t)kt * N);
        As[acol + 0][arow] = av.x;
        As[acol + 1][arow] = av.y;
        As[acol + 2][arow] = av.z;
        As[acol + 3][arow] = av.w;
        *(float4*)&Bs[brow][bcol] = bv;
        __syncthreads();
#pragma unroll
        for (int kk = 0; kk < 8; kk++) {
            float4 a0 = *(const float4*)&As[kk][ty * 8];
            float4 a1 = *(const float4*)&As[kk][ty * 8 + 4];
            ull b0 = *(const ull*)&Bs[kk][tx * 8];
            ull b1 = *(const ull*)&Bs[kk][tx * 8 + 2];
            ull b2 = *(const ull*)&Bs[kk][tx * 8 + 4];
            ull b3 = *(const ull*)&Bs[kk][tx * 8 + 6];
            ull ap[8];
            ap[0] = pack2(a0.x); ap[1] = pack2(a0.y); ap[2] = pack2(a0.z); ap[3] = pack2(a0.w);
            ap[4] = pack2(a1.x); ap[5] = pack2(a1.y); ap[6] = pack2(a1.z); ap[7] = pack2(a1.w);
#pragma unroll
            for (int r = 0; r < 8; r++) {
                fma2(acc[r][0], ap[r], b0);
                fma2(acc[r][1], ap[r], b1);
                fma2(acc[r][2], ap[r], b2);
                fma2(acc[r][3], ap[r], b3);
            }
        }
        __syncthreads();
    }

#pragma unroll
    for (int r = 0; r < 8; r++) {
        float* crow = C + (size_t)(bm + ty * 8 + r) * N + bn + tx * 8;
        float2 v0 = unpack2(acc[r][0]);
        float2 v1 = unpack2(acc[r][1]);
        float2 v2 = unpack2(acc[r][2]);
        float2 v3 = unpack2(acc[r][3]);
        *(float4*)(crow)     = make_float4(v0.x, v0.y, v1.x, v1.y);
        *(float4*)(crow + 4) = make_float4(v2.x, v2.y, v3.x, v3.y);
    }
}

// ---------------- RoPE (interleaved pairs), in place ----------------
__global__ void rope_kernel(float* __restrict__ t, const float* __restrict__ cs,
                            const float* __restrict__ sn, int heads)
{
    int idx = blockIdx.x * blockDim.x + threadIdx.x;   // grid exactly covers T*heads*64
    int i   = idx & 63;
    int h   = (idx >> 6) % heads;
    int tok = idx / (64 * heads);
    float c = cs[tok * 64 + i];
    float s = sn[tok * 64 + i];
    float* p = t + ((size_t)tok * heads + h) * HDIM + 2 * i;
    float t0 = p[0], t1 = p[1];
    p[0] = t0 * c - t1 * s;
    p[1] = t0 * s + t1 * c;
}

// ---------------- windowed flash attention, fp32, GQA ----------------
// Block: 256 threads, one (batch, head, 64-query tile). Keys streamed in 64-key tiles
// over the causal window (<=17 tiles). Online softmax. 117 KB dynamic smem.
#define QT_STR 68
#define PT_STR 68
#define ATTN_SMEM ((128 * QT_STR + 128 * QT_STR + 64 * 128 + 64 * PT_STR) * 4)

__global__ __launch_bounds__(256) void attn_kernel(
    const float* __restrict__ q, const float* __restrict__ k,
    const float* __restrict__ v, float* __restrict__ ao)
{
    extern __shared__ float sm[];
    float* Qt = sm;                      // [128][QT_STR]  Q^T (k-major), pre-scaled
    float* Kt = Qt + 128 * QT_STR;       // [128][QT_STR]  K^T (k-major)
    float* Vs = Kt + 128 * QT_STR;       // [64][128]      V row-major
    float* Pt = Vs + 64 * 128;           // [64][PT_STR]   P^T (key-major)

    const int tid  = threadIdx.x;
    const int qb   = blockIdx.x;
    const int h    = blockIdx.y;
    const int b    = blockIdx.z;
    const int kvh  = h >> 2;             // GQA: 4 q-heads per kv-head
    const int i0   = qb * 64;
    const int tok0 = b * SEQ + i0;

    const float scale = 0.08838834764831845f;  // 1/sqrt(128)

    // load Q tile (transposed, pre-scaled)
    const float* qbase = q + (size_t)tok0 * (HQ * HDIM) + h * HDIM;
#pragma unroll 8
    for (int i = tid; i < 64 * 128; i += 256) {
        int r = i >> 7, kk = i & 127;
        Qt[kk * QT_STR + r] = qbase[(size_t)r * (HQ * HDIM) + kk] * scale;
    }

    const int r0  = (tid >> 4) * 4;      // 4 query rows owned by this thread
    const int c0  = (tid & 15) * 4;      // 4 score cols
    const int c0v = (tid & 15) * 8;      // 8 output cols

    float mrow[4], lrow[4];
    ull o2[4][4];
#pragma unroll
    for (int r = 0; r < 4; r++) {
        mrow[r] = -1e30f; lrow[r] = 0.f;
#pragma unroll
        for (int u = 0; u < 4; u++) o2[r][u] = 0ull;
    }

    int jb0 = qb - 16; if (jb0 < 0) jb0 = 0;
    for (int jb = jb0; jb <= qb; jb++) {
        __syncthreads();   // previous PV done (and Qt visible on first iter)

        // load K (transposed) and V tiles
        const float* kbase = k + (size_t)(b * SEQ + jb * 64) * (KVH * HDIM) + kvh * HDIM;
        const float* vbase = v + (size_t)(b * SEQ + jb * 64) * (KVH * HDIM) + kvh * HDIM;
#pragma unroll 8
        for (int i = tid; i < 64 * 128; i += 256) {
            int j = i >> 7, kk = i & 127;
            float kv = kbase[(size_t)j * (KVH * HDIM) + kk];
            float vv = vbase[(size_t)j * (KVH * HDIM) + kk];
            Kt[kk * QT_STR + j] = kv;
            Vs[j * 128 + kk]    = vv;
        }
        __syncthreads();

        // S tile: 4x4 per thread, packed f32x2 along cols
        ull s2[4][2];
#pragma unroll
        for (int r = 0; r < 4; r++) { s2[r][0] = 0ull; s2[r][1] = 0ull; }
#pragma unroll 8
        for (int kk = 0; kk < 128; kk++) {
            float4 aq = *(const float4*)&Qt[kk * QT_STR + r0];
            ull kb0 = *(const ull*)&Kt[kk * QT_STR + c0];
            ull kb1 = *(const ull*)&Kt[kk * QT_STR + c0 + 2];
            ull a0 = pack2(aq.x), a1 = pack2(aq.y), a2 = pack2(aq.z), a3 = pack2(aq.w);
            fma2(s2[0][0], a0, kb0); fma2(s2[0][1], a0, kb1);
            fma2(s2[1][0], a1, kb0); fma2(s2[1][1], a1, kb1);
            fma2(s2[2][0], a2, kb0); fma2(s2[2][1], a2, kb1);
            fma2(s2[3][0], a3, kb0); fma2(s2[3][1], a3, kb1);
        }

        float sc[4][4];
#pragma unroll
        for (int r = 0; r < 4; r++) {
            float2 u0 = unpack2(s2[r][0]);
            float2 u1 = unpack2(s2[r][1]);
            sc[r][0] = u0.x; sc[r][1] = u0.y; sc[r][2] = u1.x; sc[r][3] = u1.y;
        }

        // mask: j <= i && i - j < WIN
        const int jg0 = jb * 64 + c0;
#pragma unroll
        for (int r = 0; r < 4; r++) {
            int iq = i0 + r0 + r;
#pragma unroll
            for (int c = 0; c < 4; c++) {
                int jg = jg0 + c;
                if (jg > iq || iq - jg >= WIN) sc[r][c] = -1e30f;
            }
        }

        // online softmax update + write P^T to smem
#pragma unroll
        for (int r = 0; r < 4; r++) {
            float rm = fmaxf(fmaxf(sc[r][0], sc[r][1]), fmaxf(sc[r][2], sc[r][3]));
#pragma unroll
            for (int off = 1; off < 16; off <<= 1)
                rm = fmaxf(rm, __shfl_xor_sync(0xffffffffu, rm, off));
            float nm = fmaxf(mrow[r], rm);
            float fct = __expf(mrow[r] - nm);
            mrow[r] = nm;
            float p0 = __expf(sc[r][0] - nm);
            float p1 = __expf(sc[r][1] - nm);
            float p2 = __expf(sc[r][2] - nm);
            float p3 = __expf(sc[r][3] - nm);
            float rs = (p0 + p1) + (p2 + p3);
#pragma unroll
            for (int off = 1; off < 16; off <<= 1)
                rs += __shfl_xor_sync(0xffffffffu, rs, off);
            lrow[r] = lrow[r] * fct + rs;
            ull f2 = pack2(fct);
#pragma unroll
            for (int u = 0; u < 4; u++) o2[r][u] = mul2(o2[r][u], f2);
            Pt[(c0 + 0) * PT_STR + r0 + r] = p0;
            Pt[(c0 + 1) * PT_STR + r0 + r] = p1;
            Pt[(c0 + 2) * PT_STR + r0 + r] = p2;
            Pt[(c0 + 3) * PT_STR + r0 + r] = p3;
        }
        __syncthreads();

        // O += P @ V : 4 rows x 8 cols per thread, packed f32x2 along cols
#pragma unroll 4
        for (int j = 0; j < 64; j++) {
            float4 pv = *(const float4*)&Pt[j * PT_STR + r0];
            ull pb0 = pack2(pv.x), pb1 = pack2(pv.y), pb2 = pack2(pv.z), pb3 = pack2(pv.w);
            const ull* vrow = (const ull*)&Vs[j * 128 + c0v];
            ull v0 = vrow[0], v1 = vrow[1], v2 = vrow[2], v3 = vrow[3];
            fma2(o2[0][0], pb0, v0); fma2(o2[0][1], pb0, v1);
            fma2(o2[0][2], pb0, v2); fma2(o2[0][3], pb0, v3);
            fma2(o2[1][0], pb1, v0); fma2(o2[1][1], pb1, v1);
            fma2(o2[1][2], pb1, v2); fma2(o2[1][3], pb1, v3);
            fma2(o2[2][0], pb2, v0); fma2(o2[2][1], pb2, v1);
            fma2(o2[2][2], pb2, v2); fma2(o2[2][3], pb2, v3);
            fma2(o2[3][0], pb3, v0); fma2(o2[3][1], pb3, v1);
            fma2(o2[3][2], pb3, v2); fma2(o2[3][3], pb3, v3);
        }
    }

    // epilogue: O / l -> g_ao
    float* aobase = ao + (size_t)tok0 * (HQ * HDIM) + h * HDIM;
#pragma unroll
    for (int r = 0; r < 4; r++) {
        float inv = 1.0f / lrow[r];
        float2 t0 = unpack2(o2[r][0]);
        float2 t1 = unpack2(o2[r][1]);
        float2 t2 = unpack2(o2[r][2]);
        float2 t3 = unpack2(o2[r][3]);
        float* dst = aobase + (size_t)(r0 + r) * (HQ * HDIM) + c0v;
        *(float4*)(dst)     = make_float4(t0.x * inv, t0.y * inv, t1.x * inv, t1.y * inv);
        *(float4*)(dst + 4) = make_float4(t2.x * inv, t2.y * inv, t3.x * inv, t3.y * inv);
    }
}

// ---------------- launch ----------------
extern "C" void kernel_launch(void* const* d_in, const int* in_sizes, int n_in,
                              void* d_out, int out_size)
{
    (void)in_sizes; (void)n_in; (void)out_size;
    const float* x  = (const float*)d_in[0];
    const float* cs = (const float*)d_in[1];
    const float* sn = (const float*)d_in[2];
    const float* wq = (const float*)d_in[3];
    const float* wk = (const float*)d_in[4];
    const float* wv = (const float*)d_in[5];
    const float* wo = (const float*)d_in[6];
    float* out = (float*)d_out;

    float *qp, *kp, *vp, *aop;
    cudaGetSymbolAddress((void**)&qp,  g_q);
    cudaGetSymbolAddress((void**)&kp,  g_k);
    cudaGetSymbolAddress((void**)&vp,  g_v);
    cudaGetSymbolAddress((void**)&aop, g_ao);

    cudaFuncSetAttribute(attn_kernel, cudaFuncAttributeMaxDynamicSharedMemorySize, ATTN_SMEM);

    dim3 blk(256);
    // QKV projections
    sgemm128<<<dim3(32, 32), blk>>>(x, wq, qp, T_TOK, HQ * HDIM,  DIMV);
    sgemm128<<<dim3(8,  32), blk>>>(x, wk, kp, T_TOK, KVH * HDIM, DIMV);
    sgemm128<<<dim3(8,  32), blk>>>(x, wv, vp, T_TOK, KVH * HDIM, DIMV);
    // RoPE on q and k
    rope_kernel<<<(T_TOK * HQ  * 64) / 256, 256>>>(qp, cs, sn, HQ);
    rope_kernel<<<(T_TOK * KVH * 64) / 256, 256>>>(kp, cs, sn, KVH);
    // windowed attention
    attn_kernel<<<dim3(SEQ / 64, HQ, BATCH), 256, ATTN_SMEM>>>(qp, kp, vp, aop);
    // output projection
    sgemm128<<<dim3(32, 32), blk>>>(aop, wo, out, T_TOK, HQ * HDIM, DIMV);
}

// round 8
// speedup vs baseline: 2.0735x; 2.0735x over previous
#include <cuda_runtime.h>
#include <cuda_bf16.h>
#include <cstdint>

// ---------------- problem constants ----------------
#define T_TOK 4096
#define DIMV  4096
#define HQ    32
#define KVH   8
#define HDIM  128
#define BATCH 2
#define SEQ   2048
#define WIN   1024

// ---------------- scratch (device globals) ----------------
__device__ float g_q [(size_t)T_TOK * HQ  * HDIM];
__device__ float g_k [(size_t)T_TOK * KVH * HDIM];
__device__ float g_v [(size_t)T_TOK * KVH * HDIM];
__device__ float g_ao[(size_t)T_TOK * HQ  * HDIM];
__device__ __nv_bfloat16 g_a_hi[(size_t)4096 * 4096];   // activation hi (x, then ao)
__device__ __nv_bfloat16 g_a_lo[(size_t)4096 * 4096];
__device__ __nv_bfloat16 g_w_hi[(size_t)4096 * 4096];   // transposed weight hi [N,K]
__device__ __nv_bfloat16 g_w_lo[(size_t)4096 * 4096];

typedef unsigned long long ull;

// ---------------- helpers ----------------
__device__ __forceinline__ uint32_t smem_u32(const void* p) {
    uint32_t a;
    asm("{ .reg .u64 t; cvta.to.shared.u64 t, %1; cvt.u32.u64 %0, t; }" : "=r"(a) : "l"(p));
    return a;
}

// ldmatrix x4, non-transposed, b16
#define LDSM4(r, addr) \
    asm volatile("ldmatrix.sync.aligned.m8n8.x4.shared.b16 {%0,%1,%2,%3}, [%4];" \
        : "=r"((r)[0]), "=r"((r)[1]), "=r"((r)[2]), "=r"((r)[3]) : "r"(addr))

// mma m16n8k16 row.col bf16 -> f32 accumulate
#define MMA16816(d, a, b0_, b1_) \
    asm volatile("mma.sync.aligned.m16n8k16.row.col.f32.bf16.bf16.f32 " \
        "{%0,%1,%2,%3}, {%4,%5,%6,%7}, {%8,%9}, {%0,%1,%2,%3};" \
        : "+f"((d)[0]), "+f"((d)[1]), "+f"((d)[2]), "+f"((d)[3]) \
        : "r"((a)[0]), "r"((a)[1]), "r"((a)[2]), "r"((a)[3]), "r"(b0_), "r"(b1_))

// ---------------- packed f32x2 helpers ----------------
__device__ __forceinline__ ull pack2(float x) {
    ull r; asm("mov.b64 %0, {%1, %1};" : "=l"(r) : "f"(x)); return r;
}
__device__ __forceinline__ float2 unpack2(ull v) {
    float2 r; asm("mov.b64 {%0, %1}, %2;" : "=f"(r.x), "=f"(r.y) : "l"(v)); return r;
}
__device__ __forceinline__ void fma2(ull& d, ull a, ull b) {
    asm("fma.rn.f32x2 %0, %1, %2, %0;" : "+l"(d) : "l"(a), "l"(b));
}
__device__ __forceinline__ ull mul2(ull a, ull b) {
    ull d; asm("mul.rn.f32x2 %0, %1, %2;" : "=l"(d) : "l"(a), "l"(b)); return d;
}

// ================= conversion kernels =================
__global__ void cvt_split(const float* __restrict__ s,
                          __nv_bfloat16* __restrict__ h, __nv_bfloat16* __restrict__ l)
{
    size_t i = ((size_t)blockIdx.x * blockDim.x + threadIdx.x) * 4;
    float4 v = *(const float4*)(s + i);
    __nv_bfloat16 h0 = __float2bfloat16(v.x);
    __nv_bfloat16 h1 = __float2bfloat16(v.y);
    __nv_bfloat16 h2 = __float2bfloat16(v.z);
    __nv_bfloat16 h3 = __float2bfloat16(v.w);
    __nv_bfloat16 l0 = __float2bfloat16(v.x - __bfloat162float(h0));
    __nv_bfloat16 l1 = __float2bfloat16(v.y - __bfloat162float(h1));
    __nv_bfloat16 l2 = __float2bfloat16(v.z - __bfloat162float(h2));
    __nv_bfloat16 l3 = __float2bfloat16(v.w - __bfloat162float(h3));
    *(__nv_bfloat162*)(h + i)     = __nv_bfloat162(h0, h1);
    *(__nv_bfloat162*)(h + i + 2) = __nv_bfloat162(h2, h3);
    *(__nv_bfloat162*)(l + i)     = __nv_bfloat162(l0, l1);
    *(__nv_bfloat162*)(l + i + 2) = __nv_bfloat162(l2, l3);
}

// W[K,N] fp32 -> Wt[N,K] (hi, lo) bf16. block (32,8), grid (N/32, K/32)
__global__ void cvt_wt(const float* __restrict__ w,
                       __nv_bfloat16* __restrict__ th, __nv_bfloat16* __restrict__ tl,
                       int K, int N)
{
    __shared__ float t[32][33];
    int n0 = blockIdx.x * 32, k0 = blockIdx.y * 32;
    int tx = threadIdx.x, ty = threadIdx.y;
#pragma unroll
    for (int j = 0; j < 4; j++)
        t[ty + 8 * j][tx] = w[(size_t)(k0 + ty + 8 * j) * N + n0 + tx];
    __syncthreads();
#pragma unroll
    for (int j = 0; j < 4; j++) {
        float v = t[tx][ty + 8 * j];
        __nv_bfloat16 h = __float2bfloat16(v);
        __nv_bfloat16 l = __float2bfloat16(v - __bfloat162float(h));
        size_t o = (size_t)(n0 + ty + 8 * j) * K + k0 + tx;
        th[o] = h; tl[o] = l;
    }
}

// ================= HMMA GEMM (arch-generic mma.sync) =================
// C[M,N] = A[M,K] @ Wt[N,K]^T, split-bf16 3-term (hh + hl + lh).
// CTA tile 128x128, BK=32, 256 threads, warp grid 4(M) x 2(N), warp tile 32x64.
// smem rows padded to 80B (40 bf16) -> ldmatrix conflict-free.
#define ROWP 40                       // padded row stride, bf16 elements
#define MAT_ELEM (128 * ROWP)         // 5120 elem = 10240 B per matrix
#define BUF_ELEM (4 * MAT_ELEM)       // Ah, Al, Bh, Bl
#define AL_OFF (MAT_ELEM)
#define BH_OFF (2 * MAT_ELEM)
#define BL_OFF (3 * MAT_ELEM)
#define GEMM_SMEM (2 * BUF_ELEM * 2)  // bytes: 81920

__global__ __launch_bounds__(256) void gemm_mma(
    const __nv_bfloat16* __restrict__ ah, const __nv_bfloat16* __restrict__ al,
    const __nv_bfloat16* __restrict__ bh, const __nv_bfloat16* __restrict__ bl,
    float* __restrict__ C, int K, int N)
{
    extern __shared__ __nv_bfloat16 sm[];
    const uint32_t s_base = smem_u32(sm);

    const int tid  = threadIdx.x;
    const int wid  = tid >> 5;
    const int lane = tid & 31;
    const int bm   = blockIdx.y * 128;
    const int bn   = blockIdx.x * 128;
    const int m_off = (wid & 3) * 32;
    const int n_off = (wid >> 2) * 64;

    // global staging coords: thread covers rows lr, lr+64; 16B chunk lc
    const int lr = tid >> 2;
    const int lc = (tid & 3) * 8;

    // ldmatrix per-lane element offsets (within a buffer)
    const int a_row = m_off + (lane & 15);
    const int a_kof = (lane >> 4) * 8;
    const int b_n   = n_off + ((lane >> 4) << 3) + (lane & 7);  // (g>>1)*8 + i, g=lane>>3
    const int b_k   = ((lane >> 3) & 1) * 8;

    float acc[2][8][4];
#pragma unroll
    for (int mi = 0; mi < 2; mi++)
#pragma unroll
        for (int nj = 0; nj < 8; nj++)
#pragma unroll
            for (int u = 0; u < 4; u++) acc[mi][nj][u] = 0.f;

    const int NIT = K >> 5;   // BK = 32
    uint4 rg[8];

    // ---- staging helpers ----
    auto LD = [&](int it) {
        size_t k0 = (size_t)it << 5;
#pragma unroll
        for (int j = 0; j < 2; j++) {
            int r = lr + j * 64;
            size_t oa = (size_t)(bm + r) * K + k0 + lc;
            size_t ob = (size_t)(bn + r) * K + k0 + lc;
            rg[j * 4 + 0] = *(const uint4*)(ah + oa);
            rg[j * 4 + 1] = *(const uint4*)(al + oa);
            rg[j * 4 + 2] = *(const uint4*)(bh + ob);
            rg[j * 4 + 3] = *(const uint4*)(bl + ob);
        }
    };
    auto ST = [&](int b) {
        __nv_bfloat16* base = sm + b * BUF_ELEM;
#pragma unroll
        for (int j = 0; j < 2; j++) {
            int r = lr + j * 64;
            int o = r * ROWP + lc;
            *(uint4*)(base + o)          = rg[j * 4 + 0];
            *(uint4*)(base + AL_OFF + o) = rg[j * 4 + 1];
            *(uint4*)(base + BH_OFF + o) = rg[j * 4 + 2];
            *(uint4*)(base + BL_OFF + o) = rg[j * 4 + 3];
        }
    };

    LD(0);
    ST(0);
    __syncthreads();

    for (int it = 0; it < NIT; it++) {
        if (it + 1 < NIT) LD(it + 1);

        const uint32_t sbuf = s_base + (uint32_t)(it & 1) * (BUF_ELEM * 2);
#pragma unroll
        for (int ks = 0; ks < 2; ks++) {
            // A fragments (hi and lo), mi = 0,1
            uint32_t ahf[2][4], alf[2][4];
            {
                uint32_t r0 = sbuf + (uint32_t)((a_row * ROWP + ks * 16 + a_kof) * 2);
                uint32_t r1 = r0 + 16 * ROWP * 2;
                LDSM4(ahf[0], r0);
                LDSM4(ahf[1], r1);
                LDSM4(alf[0], r0 + AL_OFF * 2);
                LDSM4(alf[1], r1 + AL_OFF * 2);
            }
#pragma unroll
            for (int p = 0; p < 4; p++) {
                uint32_t bb = sbuf + (uint32_t)(BH_OFF * 2) +
                              (uint32_t)(((b_n + p * 16) * ROWP + ks * 16 + b_k) * 2);
                uint32_t bhf[4], blf[4];
                LDSM4(bhf, bb);
                LDSM4(blf, bb + (BL_OFF - BH_OFF) * 2);
                const int nj0 = p * 2;
                // term hh
                MMA16816(acc[0][nj0],     ahf[0], bhf[0], bhf[1]);
                MMA16816(acc[0][nj0 + 1], ahf[0], bhf[2], bhf[3]);
                MMA16816(acc[1][nj0],     ahf[1], bhf[0], bhf[1]);
                MMA16816(acc[1][nj0 + 1], ahf[1], bhf[2], bhf[3]);
                // term hl
                MMA16816(acc[0][nj0],     ahf[0], blf[0], blf[1]);
                MMA16816(acc[0][nj0 + 1], ahf[0], blf[2], blf[3]);
                MMA16816(acc[1][nj0],     ahf[1], blf[0], blf[1]);
                MMA16816(acc[1][nj0 + 1], ahf[1], blf[2], blf[3]);
                // term lh
                MMA16816(acc[0][nj0],     alf[0], bhf[0], bhf[1]);
                MMA16816(acc[0][nj0 + 1], alf[0], bhf[2], bhf[3]);
                MMA16816(acc[1][nj0],     alf[1], bhf[0], bhf[1]);
                MMA16816(acc[1][nj0 + 1], alf[1], bhf[2], bhf[3]);
            }
        }

        if (it + 1 < NIT) ST((it + 1) & 1);
        __syncthreads();
    }

    // epilogue
    const int eg = lane >> 2, et = lane & 3;
#pragma unroll
    for (int mi = 0; mi < 2; mi++)
#pragma unroll
    for (int nj = 0; nj < 8; nj++) {
        float* c = C + (size_t)(bm + m_off + mi * 16 + eg) * N + bn + n_off + nj * 8 + et * 2;
        *(float2*)c                  = make_float2(acc[mi][nj][0], acc[mi][nj][1]);
        *(float2*)(c + (size_t)8 * N) = make_float2(acc[mi][nj][2], acc[mi][nj][3]);
    }
}

// ================= RoPE =================
__global__ void rope_kernel(float* __restrict__ t, const float* __restrict__ cs,
                            const float* __restrict__ sn, int heads)
{
    int idx = blockIdx.x * blockDim.x + threadIdx.x;
    int i   = idx & 63;
    int h   = (idx >> 6) % heads;
    int tok = idx / (64 * heads);
    float c = cs[tok * 64 + i];
    float s = sn[tok * 64 + i];
    float* p = t + ((size_t)tok * heads + h) * HDIM + 2 * i;
    float t0 = p[0], t1 = p[1];
    p[0] = t0 * c - t1 * s;
    p[1] = t0 * s + t1 * c;
}

// ================= windowed flash attention (fp32 SIMT, proven) =================
#define QT_STR 68
#define PT_STR 68
#define ATTN_SMEM ((128 * QT_STR + 128 * QT_STR + 64 * 128 + 64 * PT_STR) * 4)

__global__ __launch_bounds__(256) void attn_kernel(
    const float* __restrict__ q, const float* __restrict__ k,
    const float* __restrict__ v, float* __restrict__ ao)
{
    extern __shared__ float smf[];
    float* Qt = smf;
    float* Kt = Qt + 128 * QT_STR;
    float* Vs = Kt + 128 * QT_STR;
    float* Pt = Vs + 64 * 128;

    const int tid  = threadIdx.x;
    const int qb   = blockIdx.x;
    const int h    = blockIdx.y;
    const int b    = blockIdx.z;
    const int kvh  = h >> 2;
    const int i0   = qb * 64;
    const int tok0 = b * SEQ + i0;

    const float scale = 0.08838834764831845f;

    const float* qbase = q + (size_t)tok0 * (HQ * HDIM) + h * HDIM;
#pragma unroll 8
    for (int i = tid; i < 64 * 128; i += 256) {
        int r = i >> 7, kk = i & 127;
        Qt[kk * QT_STR + r] = qbase[(size_t)r * (HQ * HDIM) + kk] * scale;
    }

    const int r0  = (tid >> 4) * 4;
    const int c0  = (tid & 15) * 4;
    const int c0v = (tid & 15) * 8;

    float mrow[4], lrow[4];
    ull o2[4][4];
#pragma unroll
    for (int r = 0; r < 4; r++) {
        mrow[r] = -1e30f; lrow[r] = 0.f;
#pragma unroll
        for (int u = 0; u < 4; u++) o2[r][u] = 0ull;
    }

    int jb0 = qb - 16; if (jb0 < 0) jb0 = 0;
    for (int jb = jb0; jb <= qb; jb++) {
        __syncthreads();

        const float* kbase = k + (size_t)(b * SEQ + jb * 64) * (KVH * HDIM) + kvh * HDIM;
        const float* vbase = v + (size_t)(b * SEQ + jb * 64) * (KVH * HDIM) + kvh * HDIM;
#pragma unroll 8
        for (int i = tid; i < 64 * 128; i += 256) {
            int j = i >> 7, kk = i & 127;
            Kt[kk * QT_STR + j] = kbase[(size_t)j * (KVH * HDIM) + kk];
            Vs[j * 128 + kk]    = vbase[(size_t)j * (KVH * HDIM) + kk];
        }
        __syncthreads();

        ull s2[4][2];
#pragma unroll
        for (int r = 0; r < 4; r++) { s2[r][0] = 0ull; s2[r][1] = 0ull; }
#pragma unroll 8
        for (int kk = 0; kk < 128; kk++) {
            float4 aq = *(const float4*)&Qt[kk * QT_STR + r0];
            ull kb0 = *(const ull*)&Kt[kk * QT_STR + c0];
            ull kb1 = *(const ull*)&Kt[kk * QT_STR + c0 + 2];
            ull a0 = pack2(aq.x), a1 = pack2(aq.y), a2 = pack2(aq.z), a3 = pack2(aq.w);
            fma2(s2[0][0], a0, kb0); fma2(s2[0][1], a0, kb1);
            fma2(s2[1][0], a1, kb0); fma2(s2[1][1], a1, kb1);
            fma2(s2[2][0], a2, kb0); fma2(s2[2][1], a2, kb1);
            fma2(s2[3][0], a3, kb0); fma2(s2[3][1], a3, kb1);
        }

        float sc[4][4];
#pragma unroll
        for (int r = 0; r < 4; r++) {
            float2 u0 = unpack2(s2[r][0]);
            float2 u1 = unpack2(s2[r][1]);
            sc[r][0] = u0.x; sc[r][1] = u0.y; sc[r][2] = u1.x; sc[r][3] = u1.y;
        }

        const int jg0 = jb * 64 + c0;
#pragma unroll
        for (int r = 0; r < 4; r++) {
            int iq = i0 + r0 + r;
#pragma unroll
            for (int c = 0; c < 4; c++) {
                int jg = jg0 + c;
                if (jg > iq || iq - jg >= WIN) sc[r][c] = -1e30f;
            }
        }

#pragma unroll
        for (int r = 0; r < 4; r++) {
            float rm = fmaxf(fmaxf(sc[r][0], sc[r][1]), fmaxf(sc[r][2], sc[r][3]));
#pragma unroll
            for (int off = 1; off < 16; off <<= 1)
                rm = fmaxf(rm, __shfl_xor_sync(0xffffffffu, rm, off));
            float nm = fmaxf(mrow[r], rm);
            float fct = __expf(mrow[r] - nm);
            mrow[r] = nm;
            float p0 = __expf(sc[r][0] - nm);
            float p1 = __expf(sc[r][1] - nm);
            float p2 = __expf(sc[r][2] - nm);
            float p3 = __expf(sc[r][3] - nm);
            float rs = (p0 + p1) + (p2 + p3);
#pragma unroll
            for (int off = 1; off < 16; off <<= 1)
                rs += __shfl_xor_sync(0xffffffffu, rs, off);
            lrow[r] = lrow[r] * fct + rs;
            ull f2 = pack2(fct);
#pragma unroll
            for (int u = 0; u < 4; u++) o2[r][u] = mul2(o2[r][u], f2);
            Pt[(c0 + 0) * PT_STR + r0 + r] = p0;
            Pt[(c0 + 1) * PT_STR + r0 + r] = p1;
            Pt[(c0 + 2) * PT_STR + r0 + r] = p2;
            Pt[(c0 + 3) * PT_STR + r0 + r] = p3;
        }
        __syncthreads();

#pragma unroll 4
        for (int j = 0; j < 64; j++) {
            float4 pv = *(const float4*)&Pt[j * PT_STR + r0];
            ull pb0 = pack2(pv.x), pb1 = pack2(pv.y), pb2 = pack2(pv.z), pb3 = pack2(pv.w);
            const ull* vrow = (const ull*)&Vs[j * 128 + c0v];
            ull v0 = vrow[0], v1 = vrow[1], v2 = vrow[2], v3 = vrow[3];
            fma2(o2[0][0], pb0, v0); fma2(o2[0][1], pb0, v1);
            fma2(o2[0][2], pb0, v2); fma2(o2[0][3], pb0, v3);
            fma2(o2[1][0], pb1, v0); fma2(o2[1][1], pb1, v1);
            fma2(o2[1][2], pb1, v2); fma2(o2[1][3], pb1, v3);
            fma2(o2[2][0], pb2, v0); fma2(o2[2][1], pb2, v1);
            fma2(o2[2][2], pb2, v2); fma2(o2[2][3], pb2, v3);
            fma2(o2[3][0], pb3, v0); fma2(o2[3][1], pb3, v1);
            fma2(o2[3][2], pb3, v2); fma2(o2[3][3], pb3, v3);
        }
    }

    float* aobase = ao + (size_t)tok0 * (HQ * HDIM) + h * HDIM;
#pragma unroll
    for (int r = 0; r < 4; r++) {
        float inv = 1.0f / lrow[r];
        float2 t0 = unpack2(o2[r][0]);
        float2 t1 = unpack2(o2[r][1]);
        float2 t2 = unpack2(o2[r][2]);
        float2 t3 = unpack2(o2[r][3]);
        float* dst = aobase + (size_t)(r0 + r) * (HQ * HDIM) + c0v;
        *(float4*)(dst)     = make_float4(t0.x * inv, t0.y * inv, t1.x * inv, t1.y * inv);
        *(float4*)(dst + 4) = make_float4(t2.x * inv, t2.y * inv, t3.x * inv, t3.y * inv);
    }
}

// ================= launch =================
extern "C" void kernel_launch(void* const* d_in, const int* in_sizes, int n_in,
                              void* d_out, int out_size)
{
    (void)in_sizes; (void)n_in; (void)out_size;
    const float* x  = (const float*)d_in[0];
    const float* cs = (const float*)d_in[1];
    const float* sn = (const float*)d_in[2];
    const float* wq = (const float*)d_in[3];
    const float* wk = (const float*)d_in[4];
    const float* wv = (const float*)d_in[5];
    const float* wo = (const float*)d_in[6];
    float* out = (float*)d_out;

    float *qp, *kp, *vp, *aop;
    __nv_bfloat16 *ahp, *alp, *whp, *wlp;
    cudaGetSymbolAddress((void**)&qp,  g_q);
    cudaGetSymbolAddress((void**)&kp,  g_k);
    cudaGetSymbolAddress((void**)&vp,  g_v);
    cudaGetSymbolAddress((void**)&aop, g_ao);
    cudaGetSymbolAddress((void**)&ahp, g_a_hi);
    cudaGetSymbolAddress((void**)&alp, g_a_lo);
    cudaGetSymbolAddress((void**)&whp, g_w_hi);
    cudaGetSymbolAddress((void**)&wlp, g_w_lo);

    cudaFuncSetAttribute(gemm_mma,    cudaFuncAttributeMaxDynamicSharedMemorySize, GEMM_SMEM);
    cudaFuncSetAttribute(attn_kernel, cudaFuncAttributeMaxDynamicSharedMemorySize, ATTN_SMEM);

    const int NELEM = T_TOK * DIMV;
    dim3 cvtb(32, 8);

    // x -> hi/lo
    cvt_split<<<(NELEM / 4) / 256, 256>>>(x, ahp, alp);

    // Q = x @ wq
    cvt_wt<<<dim3((HQ * HDIM) / 32, DIMV / 32), cvtb>>>(wq, whp, wlp, DIMV, HQ * HDIM);
    gemm_mma<<<dim3((HQ * HDIM) / 128, T_TOK / 128), 256, GEMM_SMEM>>>(
        ahp, alp, whp, wlp, qp, DIMV, HQ * HDIM);

    // K = x @ wk
    cvt_wt<<<dim3((KVH * HDIM) / 32, DIMV / 32), cvtb>>>(wk, whp, wlp, DIMV, KVH * HDIM);
    gemm_mma<<<dim3((KVH * HDIM) / 128, T_TOK / 128), 256, GEMM_SMEM>>>(
        ahp, alp, whp, wlp, kp, DIMV, KVH * HDIM);

    // V = x @ wv
    cvt_wt<<<dim3((KVH * HDIM) / 32, DIMV / 32), cvtb>>>(wv, whp, wlp, DIMV, KVH * HDIM);
    gemm_mma<<<dim3((KVH * HDIM) / 128, T_TOK / 128), 256, GEMM_SMEM>>>(
        ahp, alp, whp, wlp, vp, DIMV, KVH * HDIM);

    // RoPE
    rope_kernel<<<(T_TOK * HQ  * 64) / 256, 256>>>(qp, cs, sn, HQ);
    rope_kernel<<<(T_TOK * KVH * 64) / 256, 256>>>(kp, cs, sn, KVH);

    // attention
    attn_kernel<<<dim3(SEQ / 64, HQ, BATCH), 256, ATTN_SMEM>>>(qp, kp, vp, aop);

    // out = ao @ wo
    cvt_split<<<(NELEM / 4) / 256, 256>>>(aop, ahp, alp);
    cvt_wt<<<dim3(DIMV / 32, (HQ * HDIM) / 32), cvtb>>>(wo, whp, wlp, HQ * HDIM, DIMV);
    gemm_mma<<<dim3(DIMV / 128, T_TOK / 128), 256, GEMM_SMEM>>>(
        ahp, alp, whp, wlp, out, HQ * HDIM, DIMV);
}

// round 9
// speedup vs baseline: 2.0737x; 1.0001x over previous
#include <cuda_runtime.h>
#include <cuda_bf16.h>
#include <cstdint>

// ---------------- problem constants ----------------
#define T_TOK 4096
#define DIMV  4096
#define HQ    32
#define KVH   8
#define HDIM  128
#define BATCH 2
#define SEQ   2048
#define WIN   1024

// ---------------- scratch (device globals) ----------------
__device__ float g_q [(size_t)T_TOK * HQ  * HDIM];
__device__ float g_k [(size_t)T_TOK * KVH * HDIM];
__device__ float g_v [(size_t)T_TOK * KVH * HDIM];
__device__ float g_ao[(size_t)T_TOK * HQ  * HDIM];
__device__ __nv_bfloat16 g_a_hi[(size_t)4096 * 4096];   // activation hi (x, then ao)
__device__ __nv_bfloat16 g_a_lo[(size_t)4096 * 4096];
__device__ __nv_bfloat16 g_w_hi[(size_t)4096 * 4096];   // transposed weight hi [N,K]
__device__ __nv_bfloat16 g_w_lo[(size_t)4096 * 4096];

typedef unsigned long long ull;

// ---------------- helpers ----------------
__device__ __forceinline__ uint32_t smem_u32(const void* p) {
    uint32_t a;
    asm("{ .reg .u64 t; cvta.to.shared.u64 t, %1; cvt.u32.u64 %0, t; }" : "=r"(a) : "l"(p));
    return a;
}

// ldmatrix x4, non-transposed, b16
#define LDSM4(r, addr) \
    asm volatile("ldmatrix.sync.aligned.m8n8.x4.shared.b16 {%0,%1,%2,%3}, [%4];" \
        : "=r"((r)[0]), "=r"((r)[1]), "=r"((r)[2]), "=r"((r)[3]) : "r"(addr))

// mma m16n8k16 row.col bf16 -> f32 accumulate
#define MMA16816(d, a, b0_, b1_) \
    asm volatile("mma.sync.aligned.m16n8k16.row.col.f32.bf16.bf16.f32 " \
        "{%0,%1,%2,%3}, {%4,%5,%6,%7}, {%8,%9}, {%0,%1,%2,%3};" \
        : "+f"((d)[0]), "+f"((d)[1]), "+f"((d)[2]), "+f"((d)[3]) \
        : "r"((a)[0]), "r"((a)[1]), "r"((a)[2]), "r"((a)[3]), "r"(b0_), "r"(b1_))

// ---------------- packed f32x2 helpers ----------------
__device__ __forceinline__ ull pack2(float x) {
    ull r; asm("mov.b64 %0, {%1, %1};" : "=l"(r) : "f"(x)); return r;
}
__device__ __forceinline__ float2 unpack2(ull v) {
    float2 r; asm("mov.b64 {%0, %1}, %2;" : "=f"(r.x), "=f"(r.y) : "l"(v)); return r;
}
__device__ __forceinline__ void fma2(ull& d, ull a, ull b) {
    asm("fma.rn.f32x2 %0, %1, %2, %0;" : "+l"(d) : "l"(a), "l"(b));
}
__device__ __forceinline__ ull mul2(ull a, ull b) {
    ull d; asm("mul.rn.f32x2 %0, %1, %2;" : "=l"(d) : "l"(a), "l"(b)); return d;
}

// ================= conversion kernels =================
__global__ void cvt_split(const float* __restrict__ s,
                          __nv_bfloat16* __restrict__ h, __nv_bfloat16* __restrict__ l)
{
    size_t i = ((size_t)blockIdx.x * blockDim.x + threadIdx.x) * 4;
    float4 v = *(const float4*)(s + i);
    __nv_bfloat16 h0 = __float2bfloat16(v.x);
    __nv_bfloat16 h1 = __float2bfloat16(v.y);
    __nv_bfloat16 h2 = __float2bfloat16(v.z);
    __nv_bfloat16 h3 = __float2bfloat16(v.w);
    __nv_bfloat16 l0 = __float2bfloat16(v.x - __bfloat162float(h0));
    __nv_bfloat16 l1 = __float2bfloat16(v.y - __bfloat162float(h1));
    __nv_bfloat16 l2 = __float2bfloat16(v.z - __bfloat162float(h2));
    __nv_bfloat16 l3 = __float2bfloat16(v.w - __bfloat162float(h3));
    *(__nv_bfloat162*)(h + i)     = __nv_bfloat162(h0, h1);
    *(__nv_bfloat162*)(h + i + 2) = __nv_bfloat162(h2, h3);
    *(__nv_bfloat162*)(l + i)     = __nv_bfloat162(l0, l1);
    *(__nv_bfloat162*)(l + i + 2) = __nv_bfloat162(l2, l3);
}

// W[K,N] fp32 -> Wt[N,K] (hi, lo) bf16. block (32,8), grid (N/32, K/32)
__global__ void cvt_wt(const float* __restrict__ w,
                       __nv_bfloat16* __restrict__ th, __nv_bfloat16* __restrict__ tl,
                       int K, int N)
{
    __shared__ float t[32][33];
    int n0 = blockIdx.x * 32, k0 = blockIdx.y * 32;
    int tx = threadIdx.x, ty = threadIdx.y;
#pragma unroll
    for (int j = 0; j < 4; j++)
        t[ty + 8 * j][tx] = w[(size_t)(k0 + ty + 8 * j) * N + n0 + tx];
    __syncthreads();
#pragma unroll
    for (int j = 0; j < 4; j++) {
        float v = t[tx][ty + 8 * j];
        __nv_bfloat16 h = __float2bfloat16(v);
        __nv_bfloat16 l = __float2bfloat16(v - __bfloat162float(h));
        size_t o = (size_t)(n0 + ty + 8 * j) * K + k0 + tx;
        th[o] = h; tl[o] = l;
    }
}

// ================= HMMA GEMM (arch-generic mma.sync) =================
// C[M,N] = A[M,K] @ Wt[N,K]^T, split-bf16 3-term (hh + hl + lh).
// CTA tile 128x128, BK=32, 256 threads, warp grid 4(M) x 2(N), warp tile 32x64.
// smem rows padded to 80B (40 bf16) -> ldmatrix conflict-free.
#define ROWP 40                       // padded row stride, bf16 elements
#define MAT_ELEM (128 * ROWP)         // 5120 elem = 10240 B per matrix
#define BUF_ELEM (4 * MAT_ELEM)       // Ah, Al, Bh, Bl
#define AL_OFF (MAT_ELEM)
#define BH_OFF (2 * MAT_ELEM)
#define BL_OFF (3 * MAT_ELEM)
#define GEMM_SMEM (2 * BUF_ELEM * 2)  // bytes: 81920

__global__ __launch_bounds__(256) void gemm_mma(
    const __nv_bfloat16* __restrict__ ah, const __nv_bfloat16* __restrict__ al,
    const __nv_bfloat16* __restrict__ bh, const __nv_bfloat16* __restrict__ bl,
    float* __restrict__ C, int K, int N)
{
    extern __shared__ __nv_bfloat16 sm[];
    const uint32_t s_base = smem_u32(sm);

    const int tid  = threadIdx.x;
    const int wid  = tid >> 5;
    const int lane = tid & 31;
    const int bm   = blockIdx.y * 128;
    const int bn   = blockIdx.x * 128;
    const int m_off = (wid & 3) * 32;
    const int n_off = (wid >> 2) * 64;

    // global staging coords: thread covers rows lr, lr+64; 16B chunk lc
    const int lr = tid >> 2;
    const int lc = (tid & 3) * 8;

    // ldmatrix per-lane element offsets (within a buffer)
    const int a_row = m_off + (lane & 15);
    const int a_kof = (lane >> 4) * 8;
    const int b_n   = n_off + ((lane >> 4) << 3) + (lane & 7);  // (g>>1)*8 + i, g=lane>>3
    const int b_k   = ((lane >> 3) & 1) * 8;

    float acc[2][8][4];
#pragma unroll
    for (int mi = 0; mi < 2; mi++)
#pragma unroll
        for (int nj = 0; nj < 8; nj++)
#pragma unroll
            for (int u = 0; u < 4; u++) acc[mi][nj][u] = 0.f;

    const int NIT = K >> 5;   // BK = 32
    uint4 rg[8];

    // ---- staging helpers ----
    auto LD = [&](int it) {
        size_t k0 = (size_t)it << 5;
#pragma unroll
        for (int j = 0; j < 2; j++) {
            int r = lr + j * 64;
            size_t oa = (size_t)(bm + r) * K + k0 + lc;
            size_t ob = (size_t)(bn + r) * K + k0 + lc;
            rg[j * 4 + 0] = *(const uint4*)(ah + oa);
            rg[j * 4 + 1] = *(const uint4*)(al + oa);
            rg[j * 4 + 2] = *(const uint4*)(bh + ob);
            rg[j * 4 + 3] = *(const uint4*)(bl + ob);
        }
    };
    auto ST = [&](int b) {
        __nv_bfloat16* base = sm + b * BUF_ELEM;
#pragma unroll
        for (int j = 0; j < 2; j++) {
            int r = lr + j * 64;
            int o = r * ROWP + lc;
            *(uint4*)(base + o)          = rg[j * 4 + 0];
            *(uint4*)(base + AL_OFF + o) = rg[j * 4 + 1];
            *(uint4*)(base + BH_OFF + o) = rg[j * 4 + 2];
            *(uint4*)(base + BL_OFF + o) = rg[j * 4 + 3];
        }
    };

    LD(0);
    ST(0);
    __syncthreads();

    for (int it = 0; it < NIT; it++) {
        if (it + 1 < NIT) LD(it + 1);

        const uint32_t sbuf = s_base + (uint32_t)(it & 1) * (BUF_ELEM * 2);
#pragma unroll
        for (int ks = 0; ks < 2; ks++) {
            // A fragments (hi and lo), mi = 0,1
            uint32_t ahf[2][4], alf[2][4];
            {
                uint32_t r0 = sbuf + (uint32_t)((a_row * ROWP + ks * 16 + a_kof) * 2);
                uint32_t r1 = r0 + 16 * ROWP * 2;
                LDSM4(ahf[0], r0);
                LDSM4(ahf[1], r1);
                LDSM4(alf[0], r0 + AL_OFF * 2);
                LDSM4(alf[1], r1 + AL_OFF * 2);
            }
#pragma unroll
            for (int p = 0; p < 4; p++) {
                uint32_t bb = sbuf + (uint32_t)(BH_OFF * 2) +
                              (uint32_t)(((b_n + p * 16) * ROWP + ks * 16 + b_k) * 2);
                uint32_t bhf[4], blf[4];
                LDSM4(bhf, bb);
                LDSM4(blf, bb + (BL_OFF - BH_OFF) * 2);
                const int nj0 = p * 2;
                // term hh
                MMA16816(acc[0][nj0],     ahf[0], bhf[0], bhf[1]);
                MMA16816(acc[0][nj0 + 1], ahf[0], bhf[2], bhf[3]);
                MMA16816(acc[1][nj0],     ahf[1], bhf[0], bhf[1]);
                MMA16816(acc[1][nj0 + 1], ahf[1], bhf[2], bhf[3]);
                // term hl
                MMA16816(acc[0][nj0],     ahf[0], blf[0], blf[1]);
                MMA16816(acc[0][nj0 + 1], ahf[0], blf[2], blf[3]);
                MMA16816(acc[1][nj0],     ahf[1], blf[0], blf[1]);
                MMA16816(acc[1][nj0 + 1], ahf[1], blf[2], blf[3]);
                // term lh
                MMA16816(acc[0][nj0],     alf[0], bhf[0], bhf[1]);
                MMA16816(acc[0][nj0 + 1], alf[0], bhf[2], bhf[3]);
                MMA16816(acc[1][nj0],     alf[1], bhf[0], bhf[1]);
                MMA16816(acc[1][nj0 + 1], alf[1], bhf[2], bhf[3]);
            }
        }

        if (it + 1 < NIT) ST((it + 1) & 1);
        __syncthreads();
    }

    // epilogue
    const int eg = lane >> 2, et = lane & 3;
#pragma unroll
    for (int mi = 0; mi < 2; mi++)
#pragma unroll
    for (int nj = 0; nj < 8; nj++) {
        float* c = C + (size_t)(bm + m_off + mi * 16 + eg) * N + bn + n_off + nj * 8 + et * 2;
        *(float2*)c                  = make_float2(acc[mi][nj][0], acc[mi][nj][1]);
        *(float2*)(c + (size_t)8 * N) = make_float2(acc[mi][nj][2], acc[mi][nj][3]);
    }
}

// ================= RoPE =================
__global__ void rope_kernel(float* __restrict__ t, const float* __restrict__ cs,
                            const float* __restrict__ sn, int heads)
{
    int idx = blockIdx.x * blockDim.x + threadIdx.x;
    int i   = idx & 63;
    int h   = (idx >> 6) % heads;
    int tok = idx / (64 * heads);
    float c = cs[tok * 64 + i];
    float s = sn[tok * 64 + i];
    float* p = t + ((size_t)tok * heads + h) * HDIM + 2 * i;
    float t0 = p[0], t1 = p[1];
    p[0] = t0 * c - t1 * s;
    p[1] = t0 * s + t1 * c;
}

// ================= windowed flash attention (fp32 SIMT, proven) =================
#define QT_STR 68
#define PT_STR 68
#define ATTN_SMEM ((128 * QT_STR + 128 * QT_STR + 64 * 128 + 64 * PT_STR) * 4)

__global__ __launch_bounds__(256) void attn_kernel(
    const float* __restrict__ q, const float* __restrict__ k,
    const float* __restrict__ v, float* __restrict__ ao)
{
    extern __shared__ float smf[];
    float* Qt = smf;
    float* Kt = Qt + 128 * QT_STR;
    float* Vs = Kt + 128 * QT_STR;
    float* Pt = Vs + 64 * 128;

    const int tid  = threadIdx.x;
    const int qb   = blockIdx.x;
    const int h    = blockIdx.y;
    const int b    = blockIdx.z;
    const int kvh  = h >> 2;
    const int i0   = qb * 64;
    const int tok0 = b * SEQ + i0;

    const float scale = 0.08838834764831845f;

    const float* qbase = q + (size_t)tok0 * (HQ * HDIM) + h * HDIM;
#pragma unroll 8
    for (int i = tid; i < 64 * 128; i += 256) {
        int r = i >> 7, kk = i & 127;
        Qt[kk * QT_STR + r] = qbase[(size_t)r * (HQ * HDIM) + kk] * scale;
    }

    const int r0  = (tid >> 4) * 4;
    const int c0  = (tid & 15) * 4;
    const int c0v = (tid & 15) * 8;

    float mrow[4], lrow[4];
    ull o2[4][4];
#pragma unroll
    for (int r = 0; r < 4; r++) {
        mrow[r] = -1e30f; lrow[r] = 0.f;
#pragma unroll
        for (int u = 0; u < 4; u++) o2[r][u] = 0ull;
    }

    int jb0 = qb - 16; if (jb0 < 0) jb0 = 0;
    for (int jb = jb0; jb <= qb; jb++) {
        __syncthreads();

        const float* kbase = k + (size_t)(b * SEQ + jb * 64) * (KVH * HDIM) + kvh * HDIM;
        const float* vbase = v + (size_t)(b * SEQ + jb * 64) * (KVH * HDIM) + kvh * HDIM;
#pragma unroll 8
        for (int i = tid; i < 64 * 128; i += 256) {
            int j = i >> 7, kk = i & 127;
            Kt[kk * QT_STR + j] = kbase[(size_t)j * (KVH * HDIM) + kk];
            Vs[j * 128 + kk]    = vbase[(size_t)j * (KVH * HDIM) + kk];
        }
        __syncthreads();

        ull s2[4][2];
#pragma unroll
        for (int r = 0; r < 4; r++) { s2[r][0] = 0ull; s2[r][1] = 0ull; }
#pragma unroll 8
        for (int kk = 0; kk < 128; kk++) {
            float4 aq = *(const float4*)&Qt[kk * QT_STR + r0];
            ull kb0 = *(const ull*)&Kt[kk * QT_STR + c0];
            ull kb1 = *(const ull*)&Kt[kk * QT_STR + c0 + 2];
            ull a0 = pack2(aq.x), a1 = pack2(aq.y), a2 = pack2(aq.z), a3 = pack2(aq.w);
            fma2(s2[0][0], a0, kb0); fma2(s2[0][1], a0, kb1);
            fma2(s2[1][0], a1, kb0); fma2(s2[1][1], a1, kb1);
            fma2(s2[2][0], a2, kb0); fma2(s2[2][1], a2, kb1);
            fma2(s2[3][0], a3, kb0); fma2(s2[3][1], a3, kb1);
        }

        float sc[4][4];
#pragma unroll
        for (int r = 0; r < 4; r++) {
            float2 u0 = unpack2(s2[r][0]);
            float2 u1 = unpack2(s2[r][1]);
            sc[r][0] = u0.x; sc[r][1] = u0.y; sc[r][2] = u1.x; sc[r][3] = u1.y;
        }

        const int jg0 = jb * 64 + c0;
#pragma unroll
        for (int r = 0; r < 4; r++) {
            int iq = i0 + r0 + r;
#pragma unroll
            for (int c = 0; c < 4; c++) {
                int jg = jg0 + c;
                if (jg > iq || iq - jg >= WIN) sc[r][c] = -1e30f;
            }
        }

#pragma unroll
        for (int r = 0; r < 4; r++) {
            float rm = fmaxf(fmaxf(sc[r][0], sc[r][1]), fmaxf(sc[r][2], sc[r][3]));
#pragma unroll
            for (int off = 1; off < 16; off <<= 1)
                rm = fmaxf(rm, __shfl_xor_sync(0xffffffffu, rm, off));
            float nm = fmaxf(mrow[r], rm);
            float fct = __expf(mrow[r] - nm);
            mrow[r] = nm;
            float p0 = __expf(sc[r][0] - nm);
            float p1 = __expf(sc[r][1] - nm);
            float p2 = __expf(sc[r][2] - nm);
            float p3 = __expf(sc[r][3] - nm);
            float rs = (p0 + p1) + (p2 + p3);
#pragma unroll
            for (int off = 1; off < 16; off <<= 1)
                rs += __shfl_xor_sync(0xffffffffu, rs, off);
            lrow[r] = lrow[r] * fct + rs;
            ull f2 = pack2(fct);
#pragma unroll
            for (int u = 0; u < 4; u++) o2[r][u] = mul2(o2[r][u], f2);
            Pt[(c0 + 0) * PT_STR + r0 + r] = p0;
            Pt[(c0 + 1) * PT_STR + r0 + r] = p1;
            Pt[(c0 + 2) * PT_STR + r0 + r] = p2;
            Pt[(c0 + 3) * PT_STR + r0 + r] = p3;
        }
        __syncthreads();

#pragma unroll 4
        for (int j = 0; j < 64; j++) {
            float4 pv = *(const float4*)&Pt[j * PT_STR + r0];
            ull pb0 = pack2(pv.x), pb1 = pack2(pv.y), pb2 = pack2(pv.z), pb3 = pack2(pv.w);
            const ull* vrow = (const ull*)&Vs[j * 128 + c0v];
            ull v0 = vrow[0], v1 = vrow[1], v2 = vrow[2], v3 = vrow[3];
            fma2(o2[0][0], pb0, v0); fma2(o2[0][1], pb0, v1);
            fma2(o2[0][2], pb0, v2); fma2(o2[0][3], pb0, v3);
            fma2(o2[1][0], pb1, v0); fma2(o2[1][1], pb1, v1);
            fma2(o2[1][2], pb1, v2); fma2(o2[1][3], pb1, v3);
            fma2(o2[2][0], pb2, v0); fma2(o2[2][1], pb2, v1);
            fma2(o2[2][2], pb2, v2); fma2(o2[2][3], pb2, v3);
            fma2(o2[3][0], pb3, v0); fma2(o2[3][1], pb3, v1);
            fma2(o2[3][2], pb3, v2); fma2(o2[3][3], pb3, v3);
        }
    }

    float* aobase = ao + (size_t)tok0 * (HQ * HDIM) + h * HDIM;
#pragma unroll
    for (int r = 0; r < 4; r++) {
        float inv = 1.0f / lrow[r];
        float2 t0 = unpack2(o2[r][0]);
        float2 t1 = unpack2(o2[r][1]);
        float2 t2 = unpack2(o2[r][2]);
        float2 t3 = unpack2(o2[r][3]);
        float* dst = aobase + (size_t)(r0 + r) * (HQ * HDIM) + c0v;
        *(float4*)(dst)     = make_float4(t0.x * inv, t0.y * inv, t1.x * inv, t1.y * inv);
        *(float4*)(dst + 4) = make_float4(t2.x * inv, t2.y * inv, t3.x * inv, t3.y * inv);
    }
}

// ================= launch =================
extern "C" void kernel_launch(void* const* d_in, const int* in_sizes, int n_in,
                              void* d_out, int out_size)
{
    (void)in_sizes; (void)n_in; (void)out_size;
    const float* x  = (const float*)d_in[0];
    const float* cs = (const float*)d_in[1];
    const float* sn = (const float*)d_in[2];
    const float* wq = (const float*)d_in[3];
    const float* wk = (const float*)d_in[4];
    const float* wv = (const float*)d_in[5];
    const float* wo = (const float*)d_in[6];
    float* out = (float*)d_out;

    float *qp, *kp, *vp, *aop;
    __nv_bfloat16 *ahp, *alp, *whp, *wlp;
    cudaGetSymbolAddress((void**)&qp,  g_q);
    cudaGetSymbolAddress((void**)&kp,  g_k);
    cudaGetSymbolAddress((void**)&vp,  g_v);
    cudaGetSymbolAddress((void**)&aop, g_ao);
    cudaGetSymbolAddress((void**)&ahp, g_a_hi);
    cudaGetSymbolAddress((void**)&alp, g_a_lo);
    cudaGetSymbolAddress((void**)&whp, g_w_hi);
    cudaGetSymbolAddress((void**)&wlp, g_w_lo);

    cudaFuncSetAttribute(gemm_mma,    cudaFuncAttributeMaxDynamicSharedMemorySize, GEMM_SMEM);
    cudaFuncSetAttribute(attn_kernel, cudaFuncAttributeMaxDynamicSharedMemorySize, ATTN_SMEM);

    const int NELEM = T_TOK * DIMV;
    dim3 cvtb(32, 8);

    // x -> hi/lo
    cvt_split<<<(NELEM / 4) / 256, 256>>>(x, ahp, alp);

    // Q = x @ wq
    cvt_wt<<<dim3((HQ * HDIM) / 32, DIMV / 32), cvtb>>>(wq, whp, wlp, DIMV, HQ * HDIM);
    gemm_mma<<<dim3((HQ * HDIM) / 128, T_TOK / 128), 256, GEMM_SMEM>>>(
        ahp, alp, whp, wlp, qp, DIMV, HQ * HDIM);

    // K = x @ wk
    cvt_wt<<<dim3((KVH * HDIM) / 32, DIMV / 32), cvtb>>>(wk, whp, wlp, DIMV, KVH * HDIM);
    gemm_mma<<<dim3((KVH * HDIM) / 128, T_TOK / 128), 256, GEMM_SMEM>>>(
        ahp, alp, whp, wlp, kp, DIMV, KVH * HDIM);

    // V = x @ wv
    cvt_wt<<<dim3((KVH * HDIM) / 32, DIMV / 32), cvtb>>>(wv, whp, wlp, DIMV, KVH * HDIM);
    gemm_mma<<<dim3((KVH * HDIM) / 128, T_TOK / 128), 256, GEMM_SMEM>>>(
        ahp, alp, whp, wlp, vp, DIMV, KVH * HDIM);

    // RoPE
    rope_kernel<<<(T_TOK * HQ  * 64) / 256, 256>>>(qp, cs, sn, HQ);
    rope_kernel<<<(T_TOK * KVH * 64) / 256, 256>>>(kp, cs, sn, KVH);

    // attention
    attn_kernel<<<dim3(SEQ / 64, HQ, BATCH), 256, ATTN_SMEM>>>(qp, kp, vp, aop);

    // out = ao @ wo
    cvt_split<<<(NELEM / 4) / 256, 256>>>(aop, ahp, alp);
    cvt_wt<<<dim3(DIMV / 32, (HQ * HDIM) / 32), cvtb>>>(wo, whp, wlp, HQ * HDIM, DIMV);
    gemm_mma<<<dim3(DIMV / 128, T_TOK / 128), 256, GEMM_SMEM>>>(
        ahp, alp, whp, wlp, out, HQ * HDIM, DIMV);
}

// round 10
// speedup vs baseline: 2.8008x; 1.3507x over previous
#include <cuda_runtime.h>
#include <cuda_bf16.h>
#include <cstdint>

// ---------------- problem constants ----------------
#define T_TOK 4096
#define DIMV  4096
#define HQ    32
#define KVH   8
#define HDIM  128
#define BATCH 2
#define SEQ   2048
#define WIN   1024

// ---------------- scratch (device globals) ----------------
__device__ float g_q [(size_t)T_TOK * HQ  * HDIM];
__device__ float g_k [(size_t)T_TOK * KVH * HDIM];
__device__ float g_v [(size_t)T_TOK * KVH * HDIM];
__device__ float g_ao[(size_t)T_TOK * HQ  * HDIM];
__device__ __nv_bfloat16 g_a_hi[(size_t)4096 * 4096];
__device__ __nv_bfloat16 g_a_lo[(size_t)4096 * 4096];
__device__ __nv_bfloat16 g_w_hi[(size_t)4096 * 4096];
__device__ __nv_bfloat16 g_w_lo[(size_t)4096 * 4096];

typedef unsigned long long ull;

// ---------------- helpers ----------------
__device__ __forceinline__ uint32_t smem_u32(const void* p) {
    uint32_t a;
    asm("{ .reg .u64 t; cvta.to.shared.u64 t, %1; cvt.u32.u64 %0, t; }" : "=r"(a) : "l"(p));
    return a;
}

#define LDSM4(r, addr) \
    asm volatile("ldmatrix.sync.aligned.m8n8.x4.shared.b16 {%0,%1,%2,%3}, [%4];" \
        : "=r"((r)[0]), "=r"((r)[1]), "=r"((r)[2]), "=r"((r)[3]) : "r"(addr))

#define LDSM4T(r, addr) \
    asm volatile("ldmatrix.sync.aligned.m8n8.x4.trans.shared.b16 {%0,%1,%2,%3}, [%4];" \
        : "=r"((r)[0]), "=r"((r)[1]), "=r"((r)[2]), "=r"((r)[3]) : "r"(addr))

#define MMA16816(d, a, b0_, b1_) \
    asm volatile("mma.sync.aligned.m16n8k16.row.col.f32.bf16.bf16.f32 " \
        "{%0,%1,%2,%3}, {%4,%5,%6,%7}, {%8,%9}, {%0,%1,%2,%3};" \
        : "+f"((d)[0]), "+f"((d)[1]), "+f"((d)[2]), "+f"((d)[3]) \
        : "r"((a)[0]), "r"((a)[1]), "r"((a)[2]), "r"((a)[3]), "r"(b0_), "r"(b1_))

// ---------------- packed f32x2 helpers ----------------
__device__ __forceinline__ ull pack2(float x) {
    ull r; asm("mov.b64 %0, {%1, %1};" : "=l"(r) : "f"(x)); return r;
}
__device__ __forceinline__ float2 unpack2(ull v) {
    float2 r; asm("mov.b64 {%0, %1}, %2;" : "=f"(r.x), "=f"(r.y) : "l"(v)); return r;
}

// split one fp32 into hi/lo bf16
__device__ __forceinline__ void split1(float v, __nv_bfloat16& h, __nv_bfloat16& l) {
    h = __float2bfloat16(v);
    l = __float2bfloat16(v - __bfloat162float(h));
}
// split float4 and store 4 hi + 4 lo bf16 (as 2x bf16x2 each)
__device__ __forceinline__ void split4_store(__nv_bfloat16* hp, __nv_bfloat16* lp, float4 v) {
    __nv_bfloat16 h0, h1, h2, h3, l0, l1, l2, l3;
    split1(v.x, h0, l0); split1(v.y, h1, l1);
    split1(v.z, h2, l2); split1(v.w, h3, l3);
    *(__nv_bfloat162*)(hp)     = __nv_bfloat162(h0, h1);
    *(__nv_bfloat162*)(hp + 2) = __nv_bfloat162(h2, h3);
    *(__nv_bfloat162*)(lp)     = __nv_bfloat162(l0, l1);
    *(__nv_bfloat162*)(lp + 2) = __nv_bfloat162(l2, l3);
}

// ================= conversion kernels =================
__global__ void cvt_split(const float* __restrict__ s,
                          __nv_bfloat16* __restrict__ h, __nv_bfloat16* __restrict__ l)
{
    size_t i = ((size_t)blockIdx.x * blockDim.x + threadIdx.x) * 4;
    float4 v = *(const float4*)(s + i);
    split4_store(h + i, l + i, v);
}

// W[K,N] fp32 -> Wt[N,K] (hi, lo) bf16. block (32,8), grid (N/32, K/32)
__global__ void cvt_wt(const float* __restrict__ w,
                       __nv_bfloat16* __restrict__ th, __nv_bfloat16* __restrict__ tl,
                       int K, int N)
{
    __shared__ float t[32][33];
    int n0 = blockIdx.x * 32, k0 = blockIdx.y * 32;
    int tx = threadIdx.x, ty = threadIdx.y;
#pragma unroll
    for (int j = 0; j < 4; j++)
        t[ty + 8 * j][tx] = w[(size_t)(k0 + ty + 8 * j) * N + n0 + tx];
    __syncthreads();
#pragma unroll
    for (int j = 0; j < 4; j++) {
        float v = t[tx][ty + 8 * j];
        __nv_bfloat16 h, l;
        split1(v, h, l);
        size_t o = (size_t)(n0 + ty + 8 * j) * K + k0 + tx;
        th[o] = h; tl[o] = l;
    }
}

// ================= HMMA GEMM (unchanged from passing R9) =================
#define ROWP 40
#define MAT_ELEM (128 * ROWP)
#define BUF_ELEM (4 * MAT_ELEM)
#define AL_OFF (MAT_ELEM)
#define BH_OFF (2 * MAT_ELEM)
#define BL_OFF (3 * MAT_ELEM)
#define GEMM_SMEM (2 * BUF_ELEM * 2)

__global__ __launch_bounds__(256) void gemm_mma(
    const __nv_bfloat16* __restrict__ ah, const __nv_bfloat16* __restrict__ al,
    const __nv_bfloat16* __restrict__ bh, const __nv_bfloat16* __restrict__ bl,
    float* __restrict__ C, int K, int N)
{
    extern __shared__ __nv_bfloat16 sm[];
    const uint32_t s_base = smem_u32(sm);

    const int tid  = threadIdx.x;
    const int wid  = tid >> 5;
    const int lane = tid & 31;
    const int bm   = blockIdx.y * 128;
    const int bn   = blockIdx.x * 128;
    const int m_off = (wid & 3) * 32;
    const int n_off = (wid >> 2) * 64;

    const int lr = tid >> 2;
    const int lc = (tid & 3) * 8;

    const int a_row = m_off + (lane & 15);
    const int a_kof = (lane >> 4) * 8;
    const int b_n   = n_off + ((lane >> 4) << 3) + (lane & 7);
    const int b_k   = ((lane >> 3) & 1) * 8;

    float acc[2][8][4];
#pragma unroll
    for (int mi = 0; mi < 2; mi++)
#pragma unroll
        for (int nj = 0; nj < 8; nj++)
#pragma unroll
            for (int u = 0; u < 4; u++) acc[mi][nj][u] = 0.f;

    const int NIT = K >> 5;
    uint4 rg[8];

    auto LD = [&](int it) {
        size_t k0 = (size_t)it << 5;
#pragma unroll
        for (int j = 0; j < 2; j++) {
            int r = lr + j * 64;
            size_t oa = (size_t)(bm + r) * K + k0 + lc;
            size_t ob = (size_t)(bn + r) * K + k0 + lc;
            rg[j * 4 + 0] = *(const uint4*)(ah + oa);
            rg[j * 4 + 1] = *(const uint4*)(al + oa);
            rg[j * 4 + 2] = *(const uint4*)(bh + ob);
            rg[j * 4 + 3] = *(const uint4*)(bl + ob);
        }
    };
    auto ST = [&](int b) {
        __nv_bfloat16* base = sm + b * BUF_ELEM;
#pragma unroll
        for (int j = 0; j < 2; j++) {
            int r = lr + j * 64;
            int o = r * ROWP + lc;
            *(uint4*)(base + o)          = rg[j * 4 + 0];
            *(uint4*)(base + AL_OFF + o) = rg[j * 4 + 1];
            *(uint4*)(base + BH_OFF + o) = rg[j * 4 + 2];
            *(uint4*)(base + BL_OFF + o) = rg[j * 4 + 3];
        }
    };

    LD(0);
    ST(0);
    __syncthreads();

    for (int it = 0; it < NIT; it++) {
        if (it + 1 < NIT) LD(it + 1);

        const uint32_t sbuf = s_base + (uint32_t)(it & 1) * (BUF_ELEM * 2);
#pragma unroll
        for (int ks = 0; ks < 2; ks++) {
            uint32_t ahf[2][4], alf[2][4];
            {
                uint32_t r0 = sbuf + (uint32_t)((a_row * ROWP + ks * 16 + a_kof) * 2);
                uint32_t r1 = r0 + 16 * ROWP * 2;
                LDSM4(ahf[0], r0);
                LDSM4(ahf[1], r1);
                LDSM4(alf[0], r0 + AL_OFF * 2);
                LDSM4(alf[1], r1 + AL_OFF * 2);
            }
#pragma unroll
            for (int p = 0; p < 4; p++) {
                uint32_t bb = sbuf + (uint32_t)(BH_OFF * 2) +
                              (uint32_t)(((b_n + p * 16) * ROWP + ks * 16 + b_k) * 2);
                uint32_t bhf[4], blf[4];
                LDSM4(bhf, bb);
                LDSM4(blf, bb + (BL_OFF - BH_OFF) * 2);
                const int nj0 = p * 2;
                MMA16816(acc[0][nj0],     ahf[0], bhf[0], bhf[1]);
                MMA16816(acc[0][nj0 + 1], ahf[0], bhf[2], bhf[3]);
                MMA16816(acc[1][nj0],     ahf[1], bhf[0], bhf[1]);
                MMA16816(acc[1][nj0 + 1], ahf[1], bhf[2], bhf[3]);
                MMA16816(acc[0][nj0],     ahf[0], blf[0], blf[1]);
                MMA16816(acc[0][nj0 + 1], ahf[0], blf[2], blf[3]);
                MMA16816(acc[1][nj0],     ahf[1], blf[0], blf[1]);
                MMA16816(acc[1][nj0 + 1], ahf[1], blf[2], blf[3]);
                MMA16816(acc[0][nj0],     alf[0], bhf[0], bhf[1]);
                MMA16816(acc[0][nj0 + 1], alf[0], bhf[2], bhf[3]);
                MMA16816(acc[1][nj0],     alf[1], bhf[0], bhf[1]);
                MMA16816(acc[1][nj0 + 1], alf[1], bhf[2], bhf[3]);
            }
        }

        if (it + 1 < NIT) ST((it + 1) & 1);
        __syncthreads();
    }

    const int eg = lane >> 2, et = lane & 3;
#pragma unroll
    for (int mi = 0; mi < 2; mi++)
#pragma unroll
    for (int nj = 0; nj < 8; nj++) {
        float* c = C + (size_t)(bm + m_off + mi * 16 + eg) * N + bn + n_off + nj * 8 + et * 2;
        *(float2*)c                  = make_float2(acc[mi][nj][0], acc[mi][nj][1]);
        *(float2*)(c + (size_t)8 * N) = make_float2(acc[mi][nj][2], acc[mi][nj][3]);
    }
}

// ================= RoPE =================
__global__ void rope_kernel(float* __restrict__ t, const float* __restrict__ cs,
                            const float* __restrict__ sn, int heads)
{
    int idx = blockIdx.x * blockDim.x + threadIdx.x;
    int i   = idx & 63;
    int h   = (idx >> 6) % heads;
    int tok = idx / (64 * heads);
    float c = cs[tok * 64 + i];
    float s = sn[tok * 64 + i];
    float* p = t + ((size_t)tok * heads + h) * HDIM + 2 * i;
    float t0 = p[0], t1 = p[1];
    p[0] = t0 * c - t1 * s;
    p[1] = t0 * s + t1 * c;
}

// ================= HMMA windowed flash attention =================
// CTA: 128 queries x 1 head. 8 warps x 16 q-rows. 64-key blocks, split-bf16 3-term
// on both QK^T and PV. Smem strides: 136 (Q/K/V), 72 (P) -> conflict-free ldmatrix.
#define AQ_STR 136
#define AP_STR 72
#define S_QH 0
#define S_QL (128 * AQ_STR)
#define S_KH (2 * 128 * AQ_STR)
#define S_KL (S_KH + 64 * AQ_STR)
#define S_VH (S_KL + 64 * AQ_STR)
#define S_VL (S_VH + 64 * AQ_STR)
#define S_PH (S_VL + 64 * AQ_STR)
#define S_PL (S_PH + 128 * AP_STR)
#define ATTN_ELEM (S_PL + 128 * AP_STR)
#define ATTN_SMEM (ATTN_ELEM * 2)

__global__ __launch_bounds__(256) void attn_mma(
    const float* __restrict__ q, const float* __restrict__ k,
    const float* __restrict__ v, float* __restrict__ ao)
{
    extern __shared__ __nv_bfloat16 smb[];
    const uint32_t s_base = smem_u32(smb);

    const int tid  = threadIdx.x;
    const int wid  = tid >> 5;
    const int lane = tid & 31;
    const int h    = blockIdx.y;
    const int b    = blockIdx.z;
    const int kvh  = h >> 2;
    const int i0   = blockIdx.x * 128;
    const int qb2  = blockIdx.x * 2;
    const int tok0 = b * SEQ + i0;

    const float scale = 0.08838834764831845f;  // 1/sqrt(128)

    // ---- load + split Q (scaled) ----
    for (int i = tid; i < 128 * 32; i += 256) {
        int r = i >> 5, c = (i & 31) * 4;
        float4 vq = *(const float4*)(q + ((size_t)(tok0 + r) * HQ + h) * HDIM + c);
        vq.x *= scale; vq.y *= scale; vq.z *= scale; vq.w *= scale;
        split4_store(smb + S_QH + r * AQ_STR + c, smb + S_QL + r * AQ_STR + c, vq);
    }

    // per-warp / per-lane geometry
    const int iw    = i0 + wid * 16;            // first query row of this warp
    const int rl    = lane >> 2;                // 0..7
    const int cq    = (lane & 3) * 2;           // acc col pair base
    // ldmatrix addressing (element offsets)
    const int a_row = wid * 16 + (lane & 15);   // Q / P fragment rows
    const int a_kof = (lane >> 4) * 8;
    const int kb_r  = ((lane >> 4) << 3) + (lane & 7);   // K fragment row pattern
    const int kb_k  = ((lane >> 3) & 1) * 8;
    const int v_row = lane & 15;                // V trans fragment row pattern
    const int v_col = (lane >> 4) * 8;

    float m_lo = -1e30f, m_hi = -1e30f, l_lo = 0.f, l_hi = 0.f;
    float o_acc[16][4];
#pragma unroll
    for (int nj = 0; nj < 16; nj++)
#pragma unroll
        for (int u = 0; u < 4; u++) o_acc[nj][u] = 0.f;

    int jb_lo = qb2 - 16; if (jb_lo < 0) jb_lo = 0;
    const int jb_hi = qb2 + 1;

    for (int jb = jb_lo; jb <= jb_hi; jb++) {
        const int j0 = jb * 64;
        __syncthreads();   // all warps done with previous K/V

        // ---- load + split K, V ----
        for (int i = tid; i < 64 * 32; i += 256) {
            int r = i >> 5, c = (i & 31) * 4;
            size_t off = ((size_t)(b * SEQ + j0 + r) * KVH + kvh) * HDIM + c;
            float4 kk = *(const float4*)(k + off);
            float4 vv = *(const float4*)(v + off);
            split4_store(smb + S_KH + r * AQ_STR + c, smb + S_KL + r * AQ_STR + c, kk);
            split4_store(smb + S_VH + r * AQ_STR + c, smb + S_VL + r * AQ_STR + c, vv);
        }
        __syncthreads();

        // per-warp skip: block fully masked for all 16 rows?
        if (j0 > iw + 15 || j0 + 63 < iw - (WIN - 1)) continue;

        // ---- S = Q K^T (3-term split) ----
        float s_acc[8][4];
#pragma unroll
        for (int nj = 0; nj < 8; nj++)
#pragma unroll
            for (int u = 0; u < 4; u++) s_acc[nj][u] = 0.f;

#pragma unroll
        for (int ks = 0; ks < 8; ks++) {
            uint32_t qh_f[4], ql_f[4];
            uint32_t aq = s_base + (uint32_t)((a_row * AQ_STR + ks * 16 + a_kof) * 2);
            LDSM4(qh_f, aq + S_QH * 2);
            LDSM4(ql_f, aq + S_QL * 2);
#pragma unroll
            for (int kp2 = 0; kp2 < 4; kp2 += 2) {
                uint32_t kh0[4], kl0[4], kh1[4], kl1[4];
                uint32_t ab0 = s_base + (uint32_t)((((kp2)     * 16 + kb_r) * AQ_STR + ks * 16 + kb_k) * 2);
                uint32_t ab1 = s_base + (uint32_t)((((kp2 + 1) * 16 + kb_r) * AQ_STR + ks * 16 + kb_k) * 2);
                LDSM4(kh0, ab0 + S_KH * 2);
                LDSM4(kl0, ab0 + S_KL * 2);
                LDSM4(kh1, ab1 + S_KH * 2);
                LDSM4(kl1, ab1 + S_KL * 2);
                const int a0 = kp2 * 2;
                // round-robin over 4 accs, distance 4 between same-acc MMAs
                MMA16816(s_acc[a0 + 0], qh_f, kh0[0], kh0[1]);
                MMA16816(s_acc[a0 + 1], qh_f, kh0[2], kh0[3]);
                MMA16816(s_acc[a0 + 2], qh_f, kh1[0], kh1[1]);
                MMA16816(s_acc[a0 + 3], qh_f, kh1[2], kh1[3]);
                MMA16816(s_acc[a0 + 0], qh_f, kl0[0], kl0[1]);
                MMA16816(s_acc[a0 + 1], qh_f, kl0[2], kl0[3]);
                MMA16816(s_acc[a0 + 2], qh_f, kl1[0], kl1[1]);
                MMA16816(s_acc[a0 + 3], qh_f, kl1[2], kl1[3]);
                MMA16816(s_acc[a0 + 0], ql_f, kh0[0], kh0[1]);
                MMA16816(s_acc[a0 + 1], ql_f, kh0[2], kh0[3]);
                MMA16816(s_acc[a0 + 2], ql_f, kh1[0], kh1[1]);
                MMA16816(s_acc[a0 + 3], ql_f, kh1[2], kh1[3]);
            }
        }

        // ---- mask + online softmax (fragment domain) ----
        const int i_lo = iw + rl;
        const int i_hi = i_lo + 8;
#pragma unroll
        for (int nj = 0; nj < 8; nj++) {
            int jg = j0 + nj * 8 + cq;
            if (jg     > i_lo || i_lo - jg     >= WIN) s_acc[nj][0] = -1e30f;
            if (jg + 1 > i_lo || i_lo - jg - 1 >= WIN) s_acc[nj][1] = -1e30f;
            if (jg     > i_hi || i_hi - jg     >= WIN) s_acc[nj][2] = -1e30f;
            if (jg + 1 > i_hi || i_hi - jg - 1 >= WIN) s_acc[nj][3] = -1e30f;
        }
        float mx_lo = -1e30f, mx_hi = -1e30f;
#pragma unroll
        for (int nj = 0; nj < 8; nj++) {
            mx_lo = fmaxf(mx_lo, fmaxf(s_acc[nj][0], s_acc[nj][1]));
            mx_hi = fmaxf(mx_hi, fmaxf(s_acc[nj][2], s_acc[nj][3]));
        }
        mx_lo = fmaxf(mx_lo, __shfl_xor_sync(0xffffffffu, mx_lo, 1));
        mx_lo = fmaxf(mx_lo, __shfl_xor_sync(0xffffffffu, mx_lo, 2));
        mx_hi = fmaxf(mx_hi, __shfl_xor_sync(0xffffffffu, mx_hi, 1));
        mx_hi = fmaxf(mx_hi, __shfl_xor_sync(0xffffffffu, mx_hi, 2));

        float mn_lo = fmaxf(m_lo, mx_lo);
        float mn_hi = fmaxf(m_hi, mx_hi);
        float f_lo = __expf(m_lo - mn_lo);
        float f_hi = __expf(m_hi - mn_hi);
        m_lo = mn_lo; m_hi = mn_hi;

        float sum_lo = 0.f, sum_hi = 0.f;
        const uint32_t p_boff = (uint32_t)(((wid * 16 + rl) * AP_STR) * 2);
#pragma unroll
        for (int nj = 0; nj < 8; nj++) {
            float p0 = __expf(s_acc[nj][0] - mn_lo);
            float p1 = __expf(s_acc[nj][1] - mn_lo);
            float p2 = __expf(s_acc[nj][2] - mn_hi);
            float p3 = __expf(s_acc[nj][3] - mn_hi);
            sum_lo += p0 + p1;
            sum_hi += p2 + p3;
            __nv_bfloat16 h0, h1, h2, h3, l0, l1, l2, l3;
            split1(p0, h0, l0); split1(p1, h1, l1);
            split1(p2, h2, l2); split1(p3, h3, l3);
            int co = nj * 8 + cq;
            *(__nv_bfloat162*)(smb + S_PH + (wid * 16 + rl) * AP_STR + co)       = __nv_bfloat162(h0, h1);
            *(__nv_bfloat162*)(smb + S_PL + (wid * 16 + rl) * AP_STR + co)       = __nv_bfloat162(l0, l1);
            *(__nv_bfloat162*)(smb + S_PH + (wid * 16 + rl + 8) * AP_STR + co)   = __nv_bfloat162(h2, h3);
            *(__nv_bfloat162*)(smb + S_PL + (wid * 16 + rl + 8) * AP_STR + co)   = __nv_bfloat162(l2, l3);
        }
        (void)p_boff;
        sum_lo += __shfl_xor_sync(0xffffffffu, sum_lo, 1);
        sum_lo += __shfl_xor_sync(0xffffffffu, sum_lo, 2);
        sum_hi += __shfl_xor_sync(0xffffffffu, sum_hi, 1);
        sum_hi += __shfl_xor_sync(0xffffffffu, sum_hi, 2);
        l_lo = l_lo * f_lo + sum_lo;
        l_hi = l_hi * f_hi + sum_hi;

        // rescale O accumulators
#pragma unroll
        for (int nj = 0; nj < 16; nj++) {
            o_acc[nj][0] *= f_lo; o_acc[nj][1] *= f_lo;
            o_acc[nj][2] *= f_hi; o_acc[nj][3] *= f_hi;
        }
        __syncwarp();

        // ---- O += P V (3-term split), B = V^T via ldmatrix.trans ----
#pragma unroll
        for (int kc = 0; kc < 4; kc++) {
            uint32_t ph_f[4], pl_f[4];
            uint32_t ap = s_base + (uint32_t)((a_row * AP_STR + kc * 16 + a_kof) * 2);
            LDSM4(ph_f, ap + S_PH * 2);
            LDSM4(pl_f, ap + S_PL * 2);
#pragma unroll
            for (int nb2 = 0; nb2 < 8; nb2 += 2) {
                uint32_t vh0[4], vl0[4], vh1[4], vl1[4];
                uint32_t av0 = s_base + (uint32_t)(((kc * 16 + v_row) * AQ_STR + (nb2)     * 16 + v_col) * 2);
                uint32_t av1 = s_base + (uint32_t)(((kc * 16 + v_row) * AQ_STR + (nb2 + 1) * 16 + v_col) * 2);
                LDSM4T(vh0, av0 + S_VH * 2);
                LDSM4T(vl0, av0 + S_VL * 2);
                LDSM4T(vh1, av1 + S_VH * 2);
                LDSM4T(vl1, av1 + S_VL * 2);
                const int a0 = nb2 * 2;
                MMA16816(o_acc[a0 + 0], ph_f, vh0[0], vh0[1]);
                MMA16816(o_acc[a0 + 1], ph_f, vh0[2], vh0[3]);
                MMA16816(o_acc[a0 + 2], ph_f, vh1[0], vh1[1]);
                MMA16816(o_acc[a0 + 3], ph_f, vh1[2], vh1[3]);
                MMA16816(o_acc[a0 + 0], ph_f, vl0[0], vl0[1]);
                MMA16816(o_acc[a0 + 1], ph_f, vl0[2], vl0[3]);
                MMA16816(o_acc[a0 + 2], ph_f, vl1[0], vl1[1]);
                MMA16816(o_acc[a0 + 3], ph_f, vl1[2], vl1[3]);
                MMA16816(o_acc[a0 + 0], pl_f, vh0[0], vh0[1]);
                MMA16816(o_acc[a0 + 1], pl_f, vh0[2], vh0[3]);
                MMA16816(o_acc[a0 + 2], pl_f, vh1[0], vh1[1]);
                MMA16816(o_acc[a0 + 3], pl_f, vh1[2], vh1[3]);
            }
        }
    }

    // ---- epilogue: O / l -> ao ----
    float inv_lo = 1.0f / l_lo;
    float inv_hi = 1.0f / l_hi;
    const int i_lo = iw + rl;
#pragma unroll
    for (int nj = 0; nj < 16; nj++) {
        int col = nj * 8 + cq;
        float* d0 = ao + ((size_t)(b * SEQ + i_lo)     * HQ + h) * HDIM + col;
        float* d1 = ao + ((size_t)(b * SEQ + i_lo + 8) * HQ + h) * HDIM + col;
        *(float2*)d0 = make_float2(o_acc[nj][0] * inv_lo, o_acc[nj][1] * inv_lo);
        *(float2*)d1 = make_float2(o_acc[nj][2] * inv_hi, o_acc[nj][3] * inv_hi);
    }
}

// ================= launch =================
extern "C" void kernel_launch(void* const* d_in, const int* in_sizes, int n_in,
                              void* d_out, int out_size)
{
    (void)in_sizes; (void)n_in; (void)out_size;
    const float* x  = (const float*)d_in[0];
    const float* cs = (const float*)d_in[1];
    const float* sn = (const float*)d_in[2];
    const float* wq = (const float*)d_in[3];
    const float* wk = (const float*)d_in[4];
    const float* wv = (const float*)d_in[5];
    const float* wo = (const float*)d_in[6];
    float* out = (float*)d_out;

    float *qp, *kp, *vp, *aop;
    __nv_bfloat16 *ahp, *alp, *whp, *wlp;
    cudaGetSymbolAddress((void**)&qp,  g_q);
    cudaGetSymbolAddress((void**)&kp,  g_k);
    cudaGetSymbolAddress((void**)&vp,  g_v);
    cudaGetSymbolAddress((void**)&aop, g_ao);
    cudaGetSymbolAddress((void**)&ahp, g_a_hi);
    cudaGetSymbolAddress((void**)&alp, g_a_lo);
    cudaGetSymbolAddress((void**)&whp, g_w_hi);
    cudaGetSymbolAddress((void**)&wlp, g_w_lo);

    cudaFuncSetAttribute(gemm_mma, cudaFuncAttributeMaxDynamicSharedMemorySize, GEMM_SMEM);
    cudaFuncSetAttribute(attn_mma, cudaFuncAttributeMaxDynamicSharedMemorySize, ATTN_SMEM);

    const int NELEM = T_TOK * DIMV;
    dim3 cvtb(32, 8);

    // x -> hi/lo
    cvt_split<<<(NELEM / 4) / 256, 256>>>(x, ahp, alp);

    // Q = x @ wq
    cvt_wt<<<dim3((HQ * HDIM) / 32, DIMV / 32), cvtb>>>(wq, whp, wlp, DIMV, HQ * HDIM);
    gemm_mma<<<dim3((HQ * HDIM) / 128, T_TOK / 128), 256, GEMM_SMEM>>>(
        ahp, alp, whp, wlp, qp, DIMV, HQ * HDIM);

    // K = x @ wk
    cvt_wt<<<dim3((KVH * HDIM) / 32, DIMV / 32), cvtb>>>(wk, whp, wlp, DIMV, KVH * HDIM);
    gemm_mma<<<dim3((KVH * HDIM) / 128, T_TOK / 128), 256, GEMM_SMEM>>>(
        ahp, alp, whp, wlp, kp, DIMV, KVH * HDIM);

    // V = x @ wv
    cvt_wt<<<dim3((KVH * HDIM) / 32, DIMV / 32), cvtb>>>(wv, whp, wlp, DIMV, KVH * HDIM);
    gemm_mma<<<dim3((KVH * HDIM) / 128, T_TOK / 128), 256, GEMM_SMEM>>>(
        ahp, alp, whp, wlp, vp, DIMV, KVH * HDIM);

    // RoPE
    rope_kernel<<<(T_TOK * HQ  * 64) / 256, 256>>>(qp, cs, sn, HQ);
    rope_kernel<<<(T_TOK * KVH * 64) / 256, 256>>>(kp, cs, sn, KVH);

    // attention (HMMA)
    attn_mma<<<dim3(SEQ / 128, HQ, BATCH), 256, ATTN_SMEM>>>(qp, kp, vp, aop);

    // out = ao @ wo
    cvt_split<<<(NELEM / 4) / 256, 256>>>(aop, ahp, alp);
    cvt_wt<<<dim3(DIMV / 32, (HQ * HDIM) / 32), cvtb>>>(wo, whp, wlp, HQ * HDIM, DIMV);
    gemm_mma<<<dim3(DIMV / 128, T_TOK / 128), 256, GEMM_SMEM>>>(
        ahp, alp, whp, wlp, out, HQ * HDIM, DIMV);
}